// round 12
// baseline (speedup 1.0000x reference)
#include <cuda_runtime.h>
#include <cuda_bf16.h>
#include <stdint.h>

#define NN 8192
#define DD 128
#define KK 4096         // K = N/2
#define NKEEP (NN - KK) // 4096
#define WPR 256         // 32-bit words per adjacency row
#define LCAP 32         // per-node unique-neighbor capacity (max out-deg ~10 here)

typedef unsigned long long u64;
typedef unsigned int u32;

// ---------------- device scratch (zero at load; invariants restored by kD)
__device__ u32   g_adj[NN * WPR];   // dup-detect bitmap; zero on entry
__device__ u32   g_list[NN * LCAP]; // unique neighbors (racy order; sorted in kB)
__device__ int   g_cnt[NN];         // unique out-degree; zero on entry
__device__ int   g_rank[NN];        // plain-store output of kC (no invariant)
__device__ float g_wf[NN];
__device__ u32   g_mw[NN];          // ascending key: smaller = higher weight
__device__ int   g_ei[NN];
__device__ int   g_ej[NN];
__device__ int   g_is64;

// ============ KA: edge decode + dup-detect + unique append (tiny) =========
__global__ void kA_decode(const void* __restrict__ edges) {
    int tid  = threadIdx.x;
    int lane = tid & 31;

    // per-warp dtype detect: odd 32-bit words of first 64 entries all zero <=> int64
    const u32* e32 = (const u32*)edges;
    u32 odd = e32[2 * lane + 1] | e32[2 * (lane + 32) + 1];
    int is64 = !__any_sync(0xffffffffu, odd != 0u);
    if (blockIdx.x == 0 && tid == 0) g_is64 = is64;

    int e = blockIdx.x * 256 + tid;
    int i, j;
    if (is64) {
        const long long* p = (const long long*)edges;
        i = (int)p[e];
        j = (int)p[NN + e];
    } else {
        const int* p = (const int*)edges;
        i = p[e];
        j = p[NN + e];
    }
    g_ei[e] = i;
    g_ej[e] = j;
    u32 bit = 1u << (j & 31);
    u32 old = atomicOr(&g_adj[i * WPR + (j >> 5)], bit);
    if (!(old & bit)) {                          // first setter owns unique edge
        int pos = atomicAdd(&g_cnt[i], 1);
        if (pos < LCAP) g_list[i * LCAP + pos] = (u32)j;
    }
}

// ============ KB: weights + keys (norms computed inline, same numerics) ===
__global__ void kB_weights(const float* __restrict__ x) {
    int tid  = threadIdx.x;
    int wid  = tid >> 5;
    int lane = tid & 31;
    int node = blockIdx.x * 8 + wid;

    int cnt = g_cnt[node];                       // unique out-degree
    if (cnt > LCAP) cnt = LCAP;
    u32 v = (lane < cnt) ? g_list[node * LCAP + lane] : 0xFFFFFFFFu;
    // 32-wide bitonic sort (ascending) — erases racy append order
    #pragma unroll
    for (int k = 2; k <= 32; k <<= 1) {
        #pragma unroll
        for (int j = k >> 1; j > 0; j >>= 1) {
            u32 o = __shfl_xor_sync(0xffffffffu, v, j);
            bool up  = ((lane & k) == 0);
            bool low = ((lane & j) == 0);
            u32 mn = v < o ? v : o;
            u32 mx = v < o ? o : v;
            v = (up == low) ? mn : mx;
        }
    }

    // own row + inline norm (identical reduce tree to old k1)
    float4 a = ((const float4*)(x + (size_t)node * DD))[lane];
    double s0 = (double)a.x * a.x + (double)a.y * a.y + (double)a.z * a.z + (double)a.w * a.w;
    #pragma unroll
    for (int o = 16; o > 0; o >>= 1) s0 += __shfl_down_sync(0xffffffffu, s0, o);
    float nif = (float)sqrt(s0);                 // lane0-exact
    float ni = fmaxf(__shfl_sync(0xffffffffu, nif, 0), 1e-12f);
    float ax = a.x / ni, ay = a.y / ni, az = a.z / ni, aw = a.w / ni;

    double acc = 0.0;
    #pragma unroll 1
    for (int ss = 0; ss < cnt; ss++) {           // ascending j (sorted)
        int j = (int)__shfl_sync(0xffffffffu, v, ss);
        float4 bv = ((const float4*)(x + (size_t)j * DD))[lane];
        double s1 = (double)bv.x * bv.x + (double)bv.y * bv.y + (double)bv.z * bv.z + (double)bv.w * bv.w;
        #pragma unroll
        for (int o = 16; o > 0; o >>= 1) s1 += __shfl_down_sync(0xffffffffu, s1, o);
        float njf = (float)sqrt(s1);
        float nj = fmaxf(__shfl_sync(0xffffffffu, njf, 0), 1e-12f);
        float bx = bv.x / nj, by = bv.y / nj, bz = bv.z / nj, bw = bv.w / nj;
        double sd = (double)ax * bx + (double)ay * by + (double)az * bz + (double)aw * bw;
        #pragma unroll
        for (int o = 16; o > 0; o >>= 1) sd += __shfl_down_sync(0xffffffffu, sd, o);
        if (lane == 0) {
            int dj = g_cnt[j];
            float dinvj = (dj > 0) ? (float)(1.0 / sqrt((double)dj)) : 0.0f;
            acc += sd * (double)dinvj;           // identical numerics to R3-R11
        }
    }
    if (lane == 0) {
        float dinvn = (cnt > 0) ? (float)(1.0 / sqrt((double)cnt)) : 0.0f;
        float wf = (float)((double)dinvn * acc);
        g_wf[node] = wf;
        u32 u = __float_as_uint(wf);
        u32 m = (u & 0x80000000u) ? ~u : (u | 0x80000000u);
        g_mw[node] = ~m;       // smaller = larger weight -> rank asc = topk order
    }
}

// ============ KC: in-block exact rank + gather ============================
// Each block loads all 8192 keys into smem; warp per node computes rank
// directly (lex order (mw, idx) == old u64 key order), writes g_rank,
// and gathers its row if selected. No atomics, no zero-invariant.
__global__ void kC_rank_gather(const float* __restrict__ x,
                               const void* __restrict__ batch,
                               float* __restrict__ out) {
    __shared__ u32 smw[NN];                      // 32KB
    int tid  = threadIdx.x;
    int wid  = tid >> 5;
    int lane = tid & 31;

    #pragma unroll
    for (int q = 0; q < 8; q++)
        ((uint4*)smw)[tid + q * 256] = ((const uint4*)g_mw)[tid + q * 256];
    __syncthreads();

    int node = blockIdx.x * 8 + wid;
    u32 mn = smw[node];
    int cnt = 0;
    const uint4* s4 = (const uint4*)smw;
    #pragma unroll 4
    for (int it = 0; it < 64; it++) {
        int idx = lane + it * 32;
        uint4 w = s4[idx];
        int j0 = idx * 4;
        cnt += (w.x < mn) || (w.x == mn && (j0 + 0) < node);
        cnt += (w.y < mn) || (w.y == mn && (j0 + 1) < node);
        cnt += (w.z < mn) || (w.z == mn && (j0 + 2) < node);
        cnt += (w.w < mn) || (w.w == mn && (j0 + 3) < node);
    }
    int r = __reduce_add_sync(0xffffffffu, cnt); // all lanes get rank
    if (lane == 0) g_rank[node] = r;

    if (r < KK) {                                // output row == rank
        float4 v = ((const float4*)(x + (size_t)node * DD))[lane];
        ((float4*)(out + (size_t)r * DD))[lane] = v;
        if (lane == 0) {
            const int OFF_PERM  = KK * DD + 2 * NKEEP;
            const int OFF_BATCH = OFF_PERM + KK;
            const int OFF_W     = OFF_BATCH + KK;
            long long bv;
            if (g_is64) bv = ((const long long*)batch)[node];
            else        bv = (long long)((const int*)batch)[node];
            out[OFF_PERM + r]  = (float)node;
            out[OFF_BATCH + r] = (float)bv;
            out[OFF_W + r]     = g_wf[node];
        }
    }
}

// ============ KD: edge emit (blocks 0..31) + cleanup (blocks 32..63) ======
__global__ void kD_emit(float* __restrict__ out) {
    int tid  = threadIdx.x;
    int lane = tid & 31;
    int wid  = tid >> 5;

    if (blockIdx.x < 32) {
        __shared__ u32 words[256];
        __shared__ int wpref[256];
        __shared__ int warpsum[8];

        #pragma unroll
        for (int q = 0; q < 32; q++) {
            int n2 = q * 256 + tid;
            int uns = (g_rank[n2] >= KK) ? 1 : 0;
            u32 w = __ballot_sync(0xffffffffu, uns);
            if (lane == 0) words[q * 8 + wid] = w;
        }
        __syncthreads();

        int c = __popc(words[tid]);
        int v = c;
        #pragma unroll
        for (int o = 1; o < 32; o <<= 1) {
            int t = __shfl_up_sync(0xffffffffu, v, o);
            if (lane >= o) v += t;
        }
        if (lane == 31) warpsum[wid] = v;
        __syncthreads();
        if (wid == 0) {
            int s = (lane < 8) ? warpsum[lane] : 0;
            #pragma unroll
            for (int o = 1; o < 8; o <<= 1) {
                int t = __shfl_up_sync(0xffffffffu, s, o);
                if (lane >= o) s += t;
            }
            if (lane < 8) warpsum[lane] = s;
        }
        __syncthreads();
        wpref[tid] = v - c + ((wid > 0) ? warpsum[wid - 1] : 0);
        __syncthreads();

        int i = blockIdx.x * 256 + tid;
        if (g_rank[i] >= KK) {               // kept edge slot
            int word = i >> 5;
            u32 w = words[word];
            int pos = wpref[word] + __popc(w & ((1u << (i & 31)) - 1u));
            int a = g_ei[i], b = g_ej[i];
            int ra = g_rank[a], rb = g_rank[b];
            const int OFF_E = KK * DD;
            out[OFF_E + pos]         = (float)((ra < KK) ? ra : 0);
            out[OFF_E + NKEEP + pos] = (float)((rb < KK) ? rb : 0);
        }
    } else {
        // restore zero-invariants (8192 edges / nodes)
        int e = (blockIdx.x - 32) * 256 + tid;
        g_adj[g_ei[e] * WPR + (g_ej[e] >> 5)] = 0u;
        g_cnt[e] = 0;
    }
}

// ---------------- launch ----------------
extern "C" void kernel_launch(void* const* d_in, const int* in_sizes, int n_in,
                              void* d_out, int out_size) {
    const float* x     = (const float*)d_in[0];
    const void*  edges = d_in[1];
    const void*  batch = d_in[2];
    float* out = (float*)d_out;

    kA_decode<<<32, 256>>>(edges);
    kB_weights<<<1024, 256>>>(x);
    kC_rank_gather<<<1024, 256>>>(x, batch, out);
    kD_emit<<<64, 256>>>(out);
}

// round 13
// speedup vs baseline: 1.0687x; 1.0687x over previous
#include <cuda_runtime.h>
#include <cuda_bf16.h>
#include <stdint.h>

#define NN 8192
#define DD 128
#define KK 4096         // K = N/2
#define NKEEP (NN - KK) // 4096
#define WPR 256         // 32-bit words per adjacency row
#define LCAP 32         // per-node unique-neighbor capacity (max out-deg ~10 here)

typedef unsigned long long u64;
typedef unsigned int u32;

// ---------------- device scratch (zero at load; invariants restored by kD)
__device__ u32   g_adj[NN * WPR];   // dup-detect bitmap; zero on entry
__device__ u32   g_list[NN * LCAP]; // unique neighbors (racy order; sorted in k3)
__device__ int   g_cnt[NN];         // unique out-degree; zero on entry
__device__ int   g_rank[NN];        // plain-store output of kC (no invariant)
__device__ float g_norm[NN];
__device__ float g_wf[NN];
__device__ u32   g_mw[NN];          // ascending key: smaller = higher weight
__device__ int   g_ei[NN];
__device__ int   g_ej[NN];
__device__ int   g_is64;

// ============ K1: norms + edge decode + dup-detect + unique append ========
// (exact R11 kernel — measured-good)
__global__ void k1_norms_pack(const float* __restrict__ x,
                              const void* __restrict__ edges) {
    int tid  = threadIdx.x;
    int wid  = tid >> 5;
    int lane = tid & 31;
    int row  = blockIdx.x * 8 + wid;

    // norms: warp per row, double sumsq
    const float4* rp = (const float4*)(x + (size_t)row * DD);
    float4 v = rp[lane];
    double s = (double)v.x * v.x + (double)v.y * v.y + (double)v.z * v.z + (double)v.w * v.w;
    #pragma unroll
    for (int o = 16; o > 0; o >>= 1) s += __shfl_down_sync(0xffffffffu, s, o);
    if (lane == 0) g_norm[row] = (float)sqrt(s);

    // blocks 0..31: decode 256 edges each
    if (blockIdx.x < 32) {
        // per-warp dtype detect: odd 32-bit words of first 64 entries all zero <=> int64
        const u32* e32 = (const u32*)edges;
        u32 odd = e32[2 * lane + 1] | e32[2 * (lane + 32) + 1];
        int is64 = !__any_sync(0xffffffffu, odd != 0u);
        if (blockIdx.x == 0 && tid == 0) g_is64 = is64;

        int e = blockIdx.x * 256 + tid;
        int i, j;
        if (is64) {
            const long long* p = (const long long*)edges;
            i = (int)p[e];
            j = (int)p[NN + e];
        } else {
            const int* p = (const int*)edges;
            i = p[e];
            j = p[NN + e];
        }
        g_ei[e] = i;
        g_ej[e] = j;
        u32 bit = 1u << (j & 31);
        u32 old = atomicOr(&g_adj[i * WPR + (j >> 5)], bit);
        if (!(old & bit)) {                          // first setter owns unique edge
            int pos = atomicAdd(&g_cnt[i], 1);
            if (pos < LCAP) g_list[i * LCAP + pos] = (u32)j;
        }
    }
}

// ============ K3: warp sort list + weights (exact R11 kernel) =============
__global__ void k3_weights(const float* __restrict__ x) {
    int tid  = threadIdx.x;
    int wid  = tid >> 5;
    int lane = tid & 31;
    int node = blockIdx.x * 8 + wid;

    int cnt = g_cnt[node];                           // unique out-degree
    u32 v = (lane < cnt) ? g_list[node * LCAP + lane] : 0xFFFFFFFFu;
    // 32-wide bitonic sort (ascending) — erases racy append order
    #pragma unroll
    for (int k = 2; k <= 32; k <<= 1) {
        #pragma unroll
        for (int j = k >> 1; j > 0; j >>= 1) {
            u32 o = __shfl_xor_sync(0xffffffffu, v, j);
            bool up  = ((lane & k) == 0);
            bool low = ((lane & j) == 0);
            u32 mn = v < o ? v : o;
            u32 mx = v < o ? o : v;
            v = (up == low) ? mn : mx;
        }
    }

    float ni = fmaxf(g_norm[node], 1e-12f);
    float4 a = ((const float4*)(x + (size_t)node * DD))[lane];
    float ax = a.x / ni, ay = a.y / ni, az = a.z / ni, aw = a.w / ni;

    double acc = 0.0;
    #pragma unroll 1
    for (int ss = 0; ss < cnt; ss++) {               // ascending j (sorted)
        int j = (int)__shfl_sync(0xffffffffu, v, ss);
        float nj = fmaxf(g_norm[j], 1e-12f);
        float4 bv = ((const float4*)(x + (size_t)j * DD))[lane];
        float bx = bv.x / nj, by = bv.y / nj, bz = bv.z / nj, bw = bv.w / nj;
        double sd = (double)ax * bx + (double)ay * by + (double)az * bz + (double)aw * bw;
        #pragma unroll
        for (int o = 16; o > 0; o >>= 1) sd += __shfl_down_sync(0xffffffffu, sd, o);
        if (lane == 0) {
            int dj = g_cnt[j];
            float dinvj = (dj > 0) ? (float)(1.0 / sqrt((double)dj)) : 0.0f;
            acc += sd * (double)dinvj;               // identical numerics to R3-R12
        }
    }
    if (lane == 0) {
        float dinvn = (cnt > 0) ? (float)(1.0 / sqrt((double)cnt)) : 0.0f;
        float wf = (float)((double)dinvn * acc);
        g_wf[node] = wf;
        u32 u = __float_as_uint(wf);
        u32 m = (u & 0x80000000u) ? ~u : (u | 0x80000000u);
        g_mw[node] = ~m;       // smaller = larger weight -> rank asc = topk order
    }
}

// ============ KC: in-block exact rank + gather ============================
// Each block loads all 8192 keys into smem; warp per node computes rank
// directly (lex order (mw, idx) == old u64 key order), writes g_rank,
// and gathers its row if selected. No atomics, no zero-invariant.
__global__ void kC_rank_gather(const float* __restrict__ x,
                               const void* __restrict__ batch,
                               float* __restrict__ out) {
    __shared__ u32 smw[NN];                      // 32KB
    int tid  = threadIdx.x;
    int wid  = tid >> 5;
    int lane = tid & 31;

    #pragma unroll
    for (int q = 0; q < 8; q++)
        ((uint4*)smw)[tid + q * 256] = ((const uint4*)g_mw)[tid + q * 256];
    __syncthreads();

    int node = blockIdx.x * 8 + wid;
    u32 mn = smw[node];
    int cnt = 0;
    const uint4* s4 = (const uint4*)smw;
    #pragma unroll 4
    for (int it = 0; it < 64; it++) {
        int idx = lane + it * 32;
        uint4 w = s4[idx];
        int j0 = idx * 4;
        cnt += (w.x < mn) || (w.x == mn && (j0 + 0) < node);
        cnt += (w.y < mn) || (w.y == mn && (j0 + 1) < node);
        cnt += (w.z < mn) || (w.z == mn && (j0 + 2) < node);
        cnt += (w.w < mn) || (w.w == mn && (j0 + 3) < node);
    }
    int r = __reduce_add_sync(0xffffffffu, cnt); // all lanes get rank
    if (lane == 0) g_rank[node] = r;

    if (r < KK) {                                // output row == rank
        float4 v = ((const float4*)(x + (size_t)node * DD))[lane];
        ((float4*)(out + (size_t)r * DD))[lane] = v;
        if (lane == 0) {
            const int OFF_PERM  = KK * DD + 2 * NKEEP;
            const int OFF_BATCH = OFF_PERM + KK;
            const int OFF_W     = OFF_BATCH + KK;
            long long bv;
            if (g_is64) bv = ((const long long*)batch)[node];
            else        bv = (long long)((const int*)batch)[node];
            out[OFF_PERM + r]  = (float)node;
            out[OFF_BATCH + r] = (float)bv;
            out[OFF_W + r]     = g_wf[node];
        }
    }
}

// ============ KD: edge emit (blocks 0..31) + cleanup (blocks 32..63) ======
__global__ void kD_emit(float* __restrict__ out) {
    int tid  = threadIdx.x;
    int lane = tid & 31;
    int wid  = tid >> 5;

    if (blockIdx.x < 32) {
        __shared__ u32 words[256];
        __shared__ int wpref[256];
        __shared__ int warpsum[8];

        #pragma unroll
        for (int q = 0; q < 32; q++) {
            int n2 = q * 256 + tid;
            int uns = (g_rank[n2] >= KK) ? 1 : 0;
            u32 w = __ballot_sync(0xffffffffu, uns);
            if (lane == 0) words[q * 8 + wid] = w;
        }
        __syncthreads();

        int c = __popc(words[tid]);
        int v = c;
        #pragma unroll
        for (int o = 1; o < 32; o <<= 1) {
            int t = __shfl_up_sync(0xffffffffu, v, o);
            if (lane >= o) v += t;
        }
        if (lane == 31) warpsum[wid] = v;
        __syncthreads();
        if (wid == 0) {
            int s = (lane < 8) ? warpsum[lane] : 0;
            #pragma unroll
            for (int o = 1; o < 8; o <<= 1) {
                int t = __shfl_up_sync(0xffffffffu, s, o);
                if (lane >= o) s += t;
            }
            if (lane < 8) warpsum[lane] = s;
        }
        __syncthreads();
        wpref[tid] = v - c + ((wid > 0) ? warpsum[wid - 1] : 0);
        __syncthreads();

        int i = blockIdx.x * 256 + tid;
        if (g_rank[i] >= KK) {               // kept edge slot
            int word = i >> 5;
            u32 w = words[word];
            int pos = wpref[word] + __popc(w & ((1u << (i & 31)) - 1u));
            int a = g_ei[i], b = g_ej[i];
            int ra = g_rank[a], rb = g_rank[b];
            const int OFF_E = KK * DD;
            out[OFF_E + pos]         = (float)((ra < KK) ? ra : 0);
            out[OFF_E + NKEEP + pos] = (float)((rb < KK) ? rb : 0);
        }
    } else {
        // restore zero-invariants (8192 edges / nodes)
        int e = (blockIdx.x - 32) * 256 + tid;
        g_adj[g_ei[e] * WPR + (g_ej[e] >> 5)] = 0u;
        g_cnt[e] = 0;
    }
}

// ---------------- launch ----------------
extern "C" void kernel_launch(void* const* d_in, const int* in_sizes, int n_in,
                              void* d_out, int out_size) {
    const float* x     = (const float*)d_in[0];
    const void*  edges = d_in[1];
    const void*  batch = d_in[2];
    float* out = (float*)d_out;

    k1_norms_pack<<<1024, 256>>>(x, edges);
    k3_weights<<<1024, 256>>>(x);
    kC_rank_gather<<<1024, 256>>>(x, batch, out);
    kD_emit<<<64, 256>>>(out);
}

// round 14
// speedup vs baseline: 1.2540x; 1.1734x over previous
#include <cuda_runtime.h>
#include <cuda_bf16.h>
#include <stdint.h>

#define NN 8192
#define DD 128
#define KK 4096         // K = N/2
#define NKEEP (NN - KK) // 4096
#define WPR 256         // 32-bit words per adjacency row
#define LCAP 32         // per-node unique-neighbor capacity (max out-deg ~10 here)

typedef unsigned long long u64;
typedef unsigned int u32;

// ---------------- device scratch (zero at load; invariants restored by k45)
__device__ u32   g_adj[NN * WPR];   // dup-detect bitmap; zero on entry
__device__ u32   g_list[NN * LCAP]; // unique neighbors (racy order; sorted in k3)
__device__ int   g_cnt[NN];         // unique out-degree; zero on entry
__device__ int   g_rank[NN];        // zeroed in k3 before k4a atomics
__device__ float g_norm[NN];
__device__ float g_wf[NN];
__device__ u32   g_mw[NN];          // ascending key: smaller = higher weight
__device__ int   g_ei[NN];
__device__ int   g_ej[NN];
__device__ int   g_is64;

// ============ K1: norms + edge decode + dup-detect + unique append ========
// (exact R11 kernel — measured-good)
__global__ void k1_norms_pack(const float* __restrict__ x,
                              const void* __restrict__ edges) {
    int tid  = threadIdx.x;
    int wid  = tid >> 5;
    int lane = tid & 31;
    int row  = blockIdx.x * 8 + wid;

    // norms: warp per row, double sumsq
    const float4* rp = (const float4*)(x + (size_t)row * DD);
    float4 v = rp[lane];
    double s = (double)v.x * v.x + (double)v.y * v.y + (double)v.z * v.z + (double)v.w * v.w;
    #pragma unroll
    for (int o = 16; o > 0; o >>= 1) s += __shfl_down_sync(0xffffffffu, s, o);
    if (lane == 0) g_norm[row] = (float)sqrt(s);

    // blocks 0..31: decode 256 edges each
    if (blockIdx.x < 32) {
        // per-warp dtype detect: odd 32-bit words of first 64 entries all zero <=> int64
        const u32* e32 = (const u32*)edges;
        u32 odd = e32[2 * lane + 1] | e32[2 * (lane + 32) + 1];
        int is64 = !__any_sync(0xffffffffu, odd != 0u);
        if (blockIdx.x == 0 && tid == 0) g_is64 = is64;

        int e = blockIdx.x * 256 + tid;
        int i, j;
        if (is64) {
            const long long* p = (const long long*)edges;
            i = (int)p[e];
            j = (int)p[NN + e];
        } else {
            const int* p = (const int*)edges;
            i = p[e];
            j = p[NN + e];
        }
        g_ei[e] = i;
        g_ej[e] = j;
        u32 bit = 1u << (j & 31);
        u32 old = atomicOr(&g_adj[i * WPR + (j >> 5)], bit);
        if (!(old & bit)) {                          // first setter owns unique edge
            int pos = atomicAdd(&g_cnt[i], 1);
            if (pos < LCAP) g_list[i * LCAP + pos] = (u32)j;
        }
    }
}

// ============ K3: warp sort list + weights (R11 numerics, pipelined loads) =
__global__ void k3_weights(const float* __restrict__ x) {
    int tid  = threadIdx.x;
    int wid  = tid >> 5;
    int lane = tid & 31;
    int node = blockIdx.x * 8 + wid;

    int cnt = g_cnt[node];                           // unique out-degree
    if (cnt > LCAP) cnt = LCAP;
    u32 v = (lane < cnt) ? g_list[node * LCAP + lane] : 0xFFFFFFFFu;
    // 32-wide bitonic sort (ascending) — erases racy append order
    #pragma unroll
    for (int k = 2; k <= 32; k <<= 1) {
        #pragma unroll
        for (int j = k >> 1; j > 0; j >>= 1) {
            u32 o = __shfl_xor_sync(0xffffffffu, v, j);
            bool up  = ((lane & k) == 0);
            bool low = ((lane & j) == 0);
            u32 mn = v < o ? v : o;
            u32 mx = v < o ? o : v;
            v = (up == low) ? mn : mx;
        }
    }

    float ni = fmaxf(g_norm[node], 1e-12f);
    float4 a = ((const float4*)(x + (size_t)node * DD))[lane];
    float ax = a.x / ni, ay = a.y / ni, az = a.z / ni, aw = a.w / ni;

    // 2-deep software pipeline over neighbors: prefetch ss+1's row/norm/deg
    // while reducing ss. Arithmetic + accumulation order identical to R11 ->
    // bit-identical weights.
    double acc = 0.0;
    float4 pb; float pn = 0.0f; int pd = 0;
    if (cnt > 0) {
        int j0 = (int)__shfl_sync(0xffffffffu, v, 0);
        pb = ((const float4*)(x + (size_t)j0 * DD))[lane];
        pn = g_norm[j0];
        pd = g_cnt[j0];
    }
    #pragma unroll 1
    for (int ss = 0; ss < cnt; ss++) {               // ascending j (sorted)
        float4 bv = pb;
        float  cn = pn;
        int    cd = pd;
        if (ss + 1 < cnt) {
            int jn = (int)__shfl_sync(0xffffffffu, v, ss + 1);
            pb = ((const float4*)(x + (size_t)jn * DD))[lane];
            pn = g_norm[jn];
            pd = g_cnt[jn];
        }
        float nj = fmaxf(cn, 1e-12f);
        float bx = bv.x / nj, by = bv.y / nj, bz = bv.z / nj, bw = bv.w / nj;
        double sd = (double)ax * bx + (double)ay * by + (double)az * bz + (double)aw * bw;
        #pragma unroll
        for (int o = 16; o > 0; o >>= 1) sd += __shfl_down_sync(0xffffffffu, sd, o);
        if (lane == 0) {
            float dinvj = (cd > 0) ? (float)(1.0 / sqrt((double)cd)) : 0.0f;
            acc += sd * (double)dinvj;               // identical numerics to R3-R13
        }
    }
    if (lane == 0) {
        float dinvn = (cnt > 0) ? (float)(1.0 / sqrt((double)cnt)) : 0.0f;
        float wf = (float)((double)dinvn * acc);
        g_wf[node] = wf;
        u32 u = __float_as_uint(wf);
        u32 m = (u & 0x80000000u) ? ~u : (u | 0x80000000u);
        g_mw[node] = ~m;       // smaller = larger weight -> rank asc = topk order
        g_rank[node] = 0;      // reset before k4a atomics (replay invariant)
    }
}

// ============ K4a: direct rank computation (exact R11 kernel) =============
// blockIdx: low 5 bits = node chunk (256 nodes), high 3 bits = j chunk (1024 keys)
__global__ void k4a_rank() {
    __shared__ u64 sk[1024];
    int tid = threadIdx.x;                   // 256 threads
    int bn = blockIdx.x & 31;
    int bj = blockIdx.x >> 5;
    int jbase = bj * 1024;
    #pragma unroll
    for (int q = 0; q < 4; q++) {
        int i = tid + q * 256;
        int j = jbase + i;
        sk[i] = ((u64)g_mw[j] << 13) | (u32)j;
    }
    __syncthreads();

    int node = bn * 256 + tid;
    u64 my = ((u64)g_mw[node] << 13) | (u32)node;
    int cnt = 0;
    const ulonglong2* sk2 = (const ulonglong2*)sk;
    #pragma unroll 8
    for (int i = 0; i < 512; i++) {          // broadcast LDS.128: 2 keys/load
        ulonglong2 p = sk2[i];
        cnt += (p.x < my) + (p.y < my);
    }
    atomicAdd(&g_rank[node], cnt);           // integer: deterministic
}

// ============ K45: fused emit + gather + invariant restore (R11-exact) ====
__global__ void k45_emit_gather(const float* __restrict__ x,
                                const void* __restrict__ batch,
                                float* __restrict__ out) {
    int tid  = threadIdx.x;
    int lane = tid & 31;
    int wid  = tid >> 5;

    // ---- gather: warp per node; output row == rank ----
    int node = blockIdx.x * 8 + wid;
    int r = g_rank[node];
    if (r < KK) {
        float4 v = ((const float4*)(x + (size_t)node * DD))[lane];
        ((float4*)(out + (size_t)r * DD))[lane] = v;
        if (lane == 0) {
            const int OFF_PERM  = KK * DD + 2 * NKEEP;
            const int OFF_BATCH = OFF_PERM + KK;
            const int OFF_W     = OFF_BATCH + KK;
            long long bv;
            if (g_is64) bv = ((const long long*)batch)[node];
            else        bv = (long long)((const int*)batch)[node];
            out[OFF_PERM + r]  = (float)node;
            out[OFF_BATCH + r] = (float)bv;
            out[OFF_W + r]     = g_wf[node];
        }
    }

    // ---- emit: blocks 0..31 ----
    if (blockIdx.x < 32) {
        __shared__ u32 words[256];
        __shared__ int wpref[256];
        __shared__ int warpsum[8];

        #pragma unroll
        for (int q = 0; q < 32; q++) {
            int n2 = q * 256 + tid;
            int uns = (g_rank[n2] >= KK) ? 1 : 0;
            u32 w = __ballot_sync(0xffffffffu, uns);
            if (lane == 0) words[q * 8 + wid] = w;
        }
        __syncthreads();

        int c = __popc(words[tid]);
        int v = c;
        #pragma unroll
        for (int o = 1; o < 32; o <<= 1) {
            int t = __shfl_up_sync(0xffffffffu, v, o);
            if (lane >= o) v += t;
        }
        if (lane == 31) warpsum[wid] = v;
        __syncthreads();
        if (wid == 0) {
            int s = (lane < 8) ? warpsum[lane] : 0;
            #pragma unroll
            for (int o = 1; o < 8; o <<= 1) {
                int t = __shfl_up_sync(0xffffffffu, s, o);
                if (lane >= o) s += t;
            }
            if (lane < 8) warpsum[lane] = s;
        }
        __syncthreads();
        wpref[tid] = v - c + ((wid > 0) ? warpsum[wid - 1] : 0);
        __syncthreads();

        int i = blockIdx.x * 256 + tid;
        if (g_rank[i] >= KK) {               // kept edge slot
            int word = i >> 5;
            u32 w = words[word];
            int pos = wpref[word] + __popc(w & ((1u << (i & 31)) - 1u));
            int a = g_ei[i], b = g_ej[i];
            int ra = g_rank[a], rb = g_rank[b];
            const int OFF_E = KK * DD;
            out[OFF_E + pos]         = (float)((ra < KK) ? ra : 0);
            out[OFF_E + NKEEP + pos] = (float)((rb < KK) ? rb : 0);
        }
    }

    // ---- restore zero-invariants: blocks 992..1023 ----
    if (blockIdx.x >= 992) {
        int e = (blockIdx.x - 992) * 256 + tid;
        g_adj[g_ei[e] * WPR + (g_ej[e] >> 5)] = 0u;
        g_cnt[e] = 0;
    }
}

// ---------------- launch ----------------
extern "C" void kernel_launch(void* const* d_in, const int* in_sizes, int n_in,
                              void* d_out, int out_size) {
    const float* x     = (const float*)d_in[0];
    const void*  edges = d_in[1];
    const void*  batch = d_in[2];
    float* out = (float*)d_out;

    k1_norms_pack<<<1024, 256>>>(x, edges);
    k3_weights<<<1024, 256>>>(x);
    k4a_rank<<<256, 256>>>();
    k45_emit_gather<<<1024, 256>>>(x, batch, out);
}

// round 15
// speedup vs baseline: 1.2931x; 1.0312x over previous
#include <cuda_runtime.h>
#include <cuda_bf16.h>
#include <stdint.h>

#define NN 8192
#define DD 128
#define KK 4096         // K = N/2
#define NKEEP (NN - KK) // 4096
#define WPR 256         // 32-bit words per adjacency row
#define LCAP 32         // per-node unique-neighbor capacity (max out-deg ~10 here)

typedef unsigned long long u64;
typedef unsigned int u32;

// PDL: dependent grid waits here until predecessor completes (full visibility)
#define GRID_DEP_WAIT() asm volatile("griddepcontrol.wait;" ::: "memory")

// ---------------- device scratch (zero at load; invariants restored by k45)
__device__ u32   g_adj[NN * WPR];   // dup-detect bitmap; zero on entry
__device__ u32   g_list[NN * LCAP]; // unique neighbors (racy order; sorted in k3)
__device__ int   g_cnt[NN];         // unique out-degree; zero on entry
__device__ int   g_rank[NN];        // zeroed in k3 before k4a atomics
__device__ float g_norm[NN];
__device__ float g_wf[NN];
__device__ u32   g_mw[NN];          // ascending key: smaller = higher weight
__device__ int   g_ei[NN];
__device__ int   g_ej[NN];
__device__ int   g_is64;

// ============ K1: norms + edge decode + dup-detect + unique append ========
__global__ void k1_norms_pack(const float* __restrict__ x,
                              const void* __restrict__ edges) {
    int tid  = threadIdx.x;
    int wid  = tid >> 5;
    int lane = tid & 31;
    int row  = blockIdx.x * 8 + wid;

    // norms: warp per row, double sumsq
    const float4* rp = (const float4*)(x + (size_t)row * DD);
    float4 v = rp[lane];
    double s = (double)v.x * v.x + (double)v.y * v.y + (double)v.z * v.z + (double)v.w * v.w;
    #pragma unroll
    for (int o = 16; o > 0; o >>= 1) s += __shfl_down_sync(0xffffffffu, s, o);
    if (lane == 0) g_norm[row] = (float)sqrt(s);

    // blocks 0..31: decode 256 edges each
    if (blockIdx.x < 32) {
        // per-warp dtype detect: odd 32-bit words of first 64 entries all zero <=> int64
        const u32* e32 = (const u32*)edges;
        u32 odd = e32[2 * lane + 1] | e32[2 * (lane + 32) + 1];
        int is64 = !__any_sync(0xffffffffu, odd != 0u);
        if (blockIdx.x == 0 && tid == 0) g_is64 = is64;

        int e = blockIdx.x * 256 + tid;
        int i, j;
        if (is64) {
            const long long* p = (const long long*)edges;
            i = (int)p[e];
            j = (int)p[NN + e];
        } else {
            const int* p = (const int*)edges;
            i = p[e];
            j = p[NN + e];
        }
        g_ei[e] = i;
        g_ej[e] = j;
        u32 bit = 1u << (j & 31);
        u32 old = atomicOr(&g_adj[i * WPR + (j >> 5)], bit);
        if (!(old & bit)) {                          // first setter owns unique edge
            int pos = atomicAdd(&g_cnt[i], 1);
            if (pos < LCAP) g_list[i * LCAP + pos] = (u32)j;
        }
    }
}

// ============ K3: warp sort list + weights (R14-exact body + PDL wait) ====
__global__ void k3_weights(const float* __restrict__ x) {
    GRID_DEP_WAIT();
    int tid  = threadIdx.x;
    int wid  = tid >> 5;
    int lane = tid & 31;
    int node = blockIdx.x * 8 + wid;

    int cnt = g_cnt[node];                           // unique out-degree
    if (cnt > LCAP) cnt = LCAP;
    u32 v = (lane < cnt) ? g_list[node * LCAP + lane] : 0xFFFFFFFFu;
    // 32-wide bitonic sort (ascending) — erases racy append order
    #pragma unroll
    for (int k = 2; k <= 32; k <<= 1) {
        #pragma unroll
        for (int j = k >> 1; j > 0; j >>= 1) {
            u32 o = __shfl_xor_sync(0xffffffffu, v, j);
            bool up  = ((lane & k) == 0);
            bool low = ((lane & j) == 0);
            u32 mn = v < o ? v : o;
            u32 mx = v < o ? o : v;
            v = (up == low) ? mn : mx;
        }
    }

    float ni = fmaxf(g_norm[node], 1e-12f);
    float4 a = ((const float4*)(x + (size_t)node * DD))[lane];
    float ax = a.x / ni, ay = a.y / ni, az = a.z / ni, aw = a.w / ni;

    // 2-deep software pipeline over neighbors (R14): prefetch ss+1 while
    // reducing ss. Arithmetic + accumulation order identical to R11-R14.
    double acc = 0.0;
    float4 pb; float pn = 0.0f; int pd = 0;
    if (cnt > 0) {
        int j0 = (int)__shfl_sync(0xffffffffu, v, 0);
        pb = ((const float4*)(x + (size_t)j0 * DD))[lane];
        pn = g_norm[j0];
        pd = g_cnt[j0];
    }
    #pragma unroll 1
    for (int ss = 0; ss < cnt; ss++) {               // ascending j (sorted)
        float4 bv = pb;
        float  cn = pn;
        int    cd = pd;
        if (ss + 1 < cnt) {
            int jn = (int)__shfl_sync(0xffffffffu, v, ss + 1);
            pb = ((const float4*)(x + (size_t)jn * DD))[lane];
            pn = g_norm[jn];
            pd = g_cnt[jn];
        }
        float nj = fmaxf(cn, 1e-12f);
        float bx = bv.x / nj, by = bv.y / nj, bz = bv.z / nj, bw = bv.w / nj;
        double sd = (double)ax * bx + (double)ay * by + (double)az * bz + (double)aw * bw;
        #pragma unroll
        for (int o = 16; o > 0; o >>= 1) sd += __shfl_down_sync(0xffffffffu, sd, o);
        if (lane == 0) {
            float dinvj = (cd > 0) ? (float)(1.0 / sqrt((double)cd)) : 0.0f;
            acc += sd * (double)dinvj;               // identical numerics to R3-R14
        }
    }
    if (lane == 0) {
        float dinvn = (cnt > 0) ? (float)(1.0 / sqrt((double)cnt)) : 0.0f;
        float wf = (float)((double)dinvn * acc);
        g_wf[node] = wf;
        u32 u = __float_as_uint(wf);
        u32 m = (u & 0x80000000u) ? ~u : (u | 0x80000000u);
        g_mw[node] = ~m;       // smaller = larger weight -> rank asc = topk order
        g_rank[node] = 0;      // reset before k4a atomics (replay invariant)
    }
}

// ============ K4a: direct rank computation (R11-exact body + PDL wait) ====
__global__ void k4a_rank() {
    GRID_DEP_WAIT();
    __shared__ u64 sk[1024];
    int tid = threadIdx.x;                   // 256 threads
    int bn = blockIdx.x & 31;
    int bj = blockIdx.x >> 5;
    int jbase = bj * 1024;
    #pragma unroll
    for (int q = 0; q < 4; q++) {
        int i = tid + q * 256;
        int j = jbase + i;
        sk[i] = ((u64)g_mw[j] << 13) | (u32)j;
    }
    __syncthreads();

    int node = bn * 256 + tid;
    u64 my = ((u64)g_mw[node] << 13) | (u32)node;
    int cnt = 0;
    const ulonglong2* sk2 = (const ulonglong2*)sk;
    #pragma unroll 8
    for (int i = 0; i < 512; i++) {          // broadcast LDS.128: 2 keys/load
        ulonglong2 p = sk2[i];
        cnt += (p.x < my) + (p.y < my);
    }
    atomicAdd(&g_rank[node], cnt);           // integer: deterministic
}

// ============ K45: fused emit + gather + restore (R11-exact + PDL wait) ===
__global__ void k45_emit_gather(const float* __restrict__ x,
                                const void* __restrict__ batch,
                                float* __restrict__ out) {
    GRID_DEP_WAIT();
    int tid  = threadIdx.x;
    int lane = tid & 31;
    int wid  = tid >> 5;

    // ---- gather: warp per node; output row == rank ----
    int node = blockIdx.x * 8 + wid;
    int r = g_rank[node];
    if (r < KK) {
        float4 v = ((const float4*)(x + (size_t)node * DD))[lane];
        ((float4*)(out + (size_t)r * DD))[lane] = v;
        if (lane == 0) {
            const int OFF_PERM  = KK * DD + 2 * NKEEP;
            const int OFF_BATCH = OFF_PERM + KK;
            const int OFF_W     = OFF_BATCH + KK;
            long long bv;
            if (g_is64) bv = ((const long long*)batch)[node];
            else        bv = (long long)((const int*)batch)[node];
            out[OFF_PERM + r]  = (float)node;
            out[OFF_BATCH + r] = (float)bv;
            out[OFF_W + r]     = g_wf[node];
        }
    }

    // ---- emit: blocks 0..31 ----
    if (blockIdx.x < 32) {
        __shared__ u32 words[256];
        __shared__ int wpref[256];
        __shared__ int warpsum[8];

        #pragma unroll
        for (int q = 0; q < 32; q++) {
            int n2 = q * 256 + tid;
            int uns = (g_rank[n2] >= KK) ? 1 : 0;
            u32 w = __ballot_sync(0xffffffffu, uns);
            if (lane == 0) words[q * 8 + wid] = w;
        }
        __syncthreads();

        int c = __popc(words[tid]);
        int v = c;
        #pragma unroll
        for (int o = 1; o < 32; o <<= 1) {
            int t = __shfl_up_sync(0xffffffffu, v, o);
            if (lane >= o) v += t;
        }
        if (lane == 31) warpsum[wid] = v;
        __syncthreads();
        if (wid == 0) {
            int s = (lane < 8) ? warpsum[lane] : 0;
            #pragma unroll
            for (int o = 1; o < 8; o <<= 1) {
                int t = __shfl_up_sync(0xffffffffu, s, o);
                if (lane >= o) s += t;
            }
            if (lane < 8) warpsum[lane] = s;
        }
        __syncthreads();
        wpref[tid] = v - c + ((wid > 0) ? warpsum[wid - 1] : 0);
        __syncthreads();

        int i = blockIdx.x * 256 + tid;
        if (g_rank[i] >= KK) {               // kept edge slot
            int word = i >> 5;
            u32 w = words[word];
            int pos = wpref[word] + __popc(w & ((1u << (i & 31)) - 1u));
            int a = g_ei[i], b = g_ej[i];
            int ra = g_rank[a], rb = g_rank[b];
            const int OFF_E = KK * DD;
            out[OFF_E + pos]         = (float)((ra < KK) ? ra : 0);
            out[OFF_E + NKEEP + pos] = (float)((rb < KK) ? rb : 0);
        }
    }

    // ---- restore zero-invariants: blocks 992..1023 ----
    if (blockIdx.x >= 992) {
        int e = (blockIdx.x - 992) * 256 + tid;
        g_adj[g_ei[e] * WPR + (g_ej[e] >> 5)] = 0u;
        g_cnt[e] = 0;
    }
}

// ---------------- launch (PDL-chained) ----------------
static void launch_pdl(void* fn, dim3 grid, dim3 block, void** args) {
    cudaLaunchConfig_t cfg = {};
    cfg.gridDim = grid;
    cfg.blockDim = block;
    cudaLaunchAttribute attr[1];
    attr[0].id = cudaLaunchAttributeProgrammaticStreamSerialization;
    attr[0].val.programmaticStreamSerializationAllowed = 1;
    cfg.attrs = attr;
    cfg.numAttrs = 1;
    cudaLaunchKernelExC(&cfg, fn, args);
}

extern "C" void kernel_launch(void* const* d_in, const int* in_sizes, int n_in,
                              void* d_out, int out_size) {
    const float* x     = (const float*)d_in[0];
    const void*  edges = d_in[1];
    const void*  batch = d_in[2];
    float* out = (float*)d_out;

    k1_norms_pack<<<1024, 256>>>(x, edges);

    {   // k3 (dependent on k1)
        void* args[] = { (void*)&x };
        launch_pdl((void*)k3_weights, dim3(1024), dim3(256), args);
    }
    {   // k4a (dependent on k3)
        void* args[] = {};
        launch_pdl((void*)k4a_rank, dim3(256), dim3(256), args);
    }
    {   // k45 (dependent on k4a)
        void* args[] = { (void*)&x, (void*)&batch, (void*)&out };
        launch_pdl((void*)k45_emit_gather, dim3(1024), dim3(256), args);
    }
}

// round 16
// speedup vs baseline: 1.2958x; 1.0021x over previous
#include <cuda_runtime.h>
#include <cuda_bf16.h>
#include <stdint.h>

#define NN 8192
#define DD 128
#define KK 4096         // K = N/2
#define NKEEP (NN - KK) // 4096
#define WPR 256         // 32-bit words per adjacency row
#define LCAP 32         // per-node unique-neighbor capacity (max out-deg ~10 here)

typedef unsigned long long u64;
typedef unsigned int u32;

// PDL: dependent grid waits here until predecessor completes (full visibility)
#define GRID_DEP_WAIT() asm volatile("griddepcontrol.wait;" ::: "memory")

// ---------------- device scratch (zero at load; invariants restored by k45)
__device__ u32   g_adj[NN * WPR];   // dup-detect bitmap; zero on entry
__device__ u32   g_list[NN * LCAP]; // unique neighbors (racy order; sorted in k3)
__device__ int   g_cnt[NN];         // unique out-degree; zero on entry
__device__ int   g_rank[NN];        // zeroed in k3 before k4a atomics
__device__ float g_norm[NN];
__device__ float g_wf[NN];
__device__ u32   g_mw[NN];          // ascending key: smaller = higher weight
__device__ int   g_ei[NN];
__device__ int   g_ej[NN];
__device__ int   g_is64;

// ============ K1: norms (warp per 4 rows, MLP=4) + edge decode ============
__global__ void k1_norms_pack(const float* __restrict__ x,
                              const void* __restrict__ edges) {
    int tid  = threadIdx.x;
    int wid  = tid >> 5;
    int lane = tid & 31;
    int row0 = blockIdx.x * 32 + wid * 4;            // 256 blocks x 8 warps x 4 rows

    // issue all 4 independent row loads first (MLP), then reduce each
    float4 v0 = ((const float4*)(x + (size_t)(row0 + 0) * DD))[lane];
    float4 v1 = ((const float4*)(x + (size_t)(row0 + 1) * DD))[lane];
    float4 v2 = ((const float4*)(x + (size_t)(row0 + 2) * DD))[lane];
    float4 v3 = ((const float4*)(x + (size_t)(row0 + 3) * DD))[lane];
    double s0 = (double)v0.x * v0.x + (double)v0.y * v0.y + (double)v0.z * v0.z + (double)v0.w * v0.w;
    double s1 = (double)v1.x * v1.x + (double)v1.y * v1.y + (double)v1.z * v1.z + (double)v1.w * v1.w;
    double s2 = (double)v2.x * v2.x + (double)v2.y * v2.y + (double)v2.z * v2.z + (double)v2.w * v2.w;
    double s3 = (double)v3.x * v3.x + (double)v3.y * v3.y + (double)v3.z * v3.z + (double)v3.w * v3.w;
    #pragma unroll
    for (int o = 16; o > 0; o >>= 1) {
        s0 += __shfl_down_sync(0xffffffffu, s0, o);
        s1 += __shfl_down_sync(0xffffffffu, s1, o);
        s2 += __shfl_down_sync(0xffffffffu, s2, o);
        s3 += __shfl_down_sync(0xffffffffu, s3, o);
    }
    if (lane == 0) {
        g_norm[row0 + 0] = (float)sqrt(s0);
        g_norm[row0 + 1] = (float)sqrt(s1);
        g_norm[row0 + 2] = (float)sqrt(s2);
        g_norm[row0 + 3] = (float)sqrt(s3);
    }

    // blocks 0..31: decode 256 edges each
    if (blockIdx.x < 32) {
        // per-warp dtype detect: odd 32-bit words of first 64 entries all zero <=> int64
        const u32* e32 = (const u32*)edges;
        u32 odd = e32[2 * lane + 1] | e32[2 * (lane + 32) + 1];
        int is64 = !__any_sync(0xffffffffu, odd != 0u);
        if (blockIdx.x == 0 && tid == 0) g_is64 = is64;

        int e = blockIdx.x * 256 + tid;
        int i, j;
        if (is64) {
            const long long* p = (const long long*)edges;
            i = (int)p[e];
            j = (int)p[NN + e];
        } else {
            const int* p = (const int*)edges;
            i = p[e];
            j = p[NN + e];
        }
        g_ei[e] = i;
        g_ej[e] = j;
        u32 bit = 1u << (j & 31);
        u32 old = atomicOr(&g_adj[i * WPR + (j >> 5)], bit);
        if (!(old & bit)) {                          // first setter owns unique edge
            int pos = atomicAdd(&g_cnt[i], 1);
            if (pos < LCAP) g_list[i * LCAP + pos] = (u32)j;
        }
    }
}

// ============ K3: warp sort list + weights (R14-exact body + PDL wait) ====
__global__ void k3_weights(const float* __restrict__ x) {
    GRID_DEP_WAIT();
    int tid  = threadIdx.x;
    int wid  = tid >> 5;
    int lane = tid & 31;
    int node = blockIdx.x * 8 + wid;

    int cnt = g_cnt[node];                           // unique out-degree
    if (cnt > LCAP) cnt = LCAP;
    u32 v = (lane < cnt) ? g_list[node * LCAP + lane] : 0xFFFFFFFFu;
    // 32-wide bitonic sort (ascending) — erases racy append order
    #pragma unroll
    for (int k = 2; k <= 32; k <<= 1) {
        #pragma unroll
        for (int j = k >> 1; j > 0; j >>= 1) {
            u32 o = __shfl_xor_sync(0xffffffffu, v, j);
            bool up  = ((lane & k) == 0);
            bool low = ((lane & j) == 0);
            u32 mn = v < o ? v : o;
            u32 mx = v < o ? o : v;
            v = (up == low) ? mn : mx;
        }
    }

    float ni = fmaxf(g_norm[node], 1e-12f);
    float4 a = ((const float4*)(x + (size_t)node * DD))[lane];
    float ax = a.x / ni, ay = a.y / ni, az = a.z / ni, aw = a.w / ni;

    // 2-deep software pipeline over neighbors (R14): prefetch ss+1 while
    // reducing ss. Arithmetic + accumulation order identical to R11-R15.
    double acc = 0.0;
    float4 pb; float pn = 0.0f; int pd = 0;
    if (cnt > 0) {
        int j0 = (int)__shfl_sync(0xffffffffu, v, 0);
        pb = ((const float4*)(x + (size_t)j0 * DD))[lane];
        pn = g_norm[j0];
        pd = g_cnt[j0];
    }
    #pragma unroll 1
    for (int ss = 0; ss < cnt; ss++) {               // ascending j (sorted)
        float4 bv = pb;
        float  cn = pn;
        int    cd = pd;
        if (ss + 1 < cnt) {
            int jn = (int)__shfl_sync(0xffffffffu, v, ss + 1);
            pb = ((const float4*)(x + (size_t)jn * DD))[lane];
            pn = g_norm[jn];
            pd = g_cnt[jn];
        }
        float nj = fmaxf(cn, 1e-12f);
        float bx = bv.x / nj, by = bv.y / nj, bz = bv.z / nj, bw = bv.w / nj;
        double sd = (double)ax * bx + (double)ay * by + (double)az * bz + (double)aw * bw;
        #pragma unroll
        for (int o = 16; o > 0; o >>= 1) sd += __shfl_down_sync(0xffffffffu, sd, o);
        if (lane == 0) {
            float dinvj = (cd > 0) ? (float)(1.0 / sqrt((double)cd)) : 0.0f;
            acc += sd * (double)dinvj;               // identical numerics to R3-R15
        }
    }
    if (lane == 0) {
        float dinvn = (cnt > 0) ? (float)(1.0 / sqrt((double)cnt)) : 0.0f;
        float wf = (float)((double)dinvn * acc);
        g_wf[node] = wf;
        u32 u = __float_as_uint(wf);
        u32 m = (u & 0x80000000u) ? ~u : (u | 0x80000000u);
        g_mw[node] = ~m;       // smaller = larger weight -> rank asc = topk order
        g_rank[node] = 0;      // reset before k4a atomics (replay invariant)
    }
}

// ============ K4a: rank, 512 blocks (32 node-chunks x 16 key-chunks) ======
__global__ void k4a_rank() {
    GRID_DEP_WAIT();
    __shared__ u64 sk[512];
    int tid = threadIdx.x;                   // 256 threads
    int bn = blockIdx.x & 31;                // node chunk (256 nodes)
    int bj = blockIdx.x >> 5;                // key chunk (512 keys)
    int jbase = bj * 512;
    #pragma unroll
    for (int q = 0; q < 2; q++) {
        int i = tid + q * 256;
        int j = jbase + i;
        sk[i] = ((u64)g_mw[j] << 13) | (u32)j;
    }
    __syncthreads();

    int node = bn * 256 + tid;
    u64 my = ((u64)g_mw[node] << 13) | (u32)node;
    int cnt = 0;
    const ulonglong2* sk2 = (const ulonglong2*)sk;
    #pragma unroll 8
    for (int i = 0; i < 256; i++) {          // broadcast LDS.128: 2 keys/load
        ulonglong2 p = sk2[i];
        cnt += (p.x < my) + (p.y < my);
    }
    atomicAdd(&g_rank[node], cnt);           // integer: deterministic
}

// ============ K45: emit + gather (warp per 2 nodes, MLP=2) + restore ======
__global__ void k45_emit_gather(const float* __restrict__ x,
                                const void* __restrict__ batch,
                                float* __restrict__ out) {
    GRID_DEP_WAIT();
    int tid  = threadIdx.x;
    int lane = tid & 31;
    int wid  = tid >> 5;

    // ---- gather: warp per 2 nodes; output row == rank ----
    int n0 = blockIdx.x * 16 + wid * 2;              // 512 blocks x 8 warps x 2 nodes
    int n1 = n0 + 1;
    int r0 = g_rank[n0];
    int r1 = g_rank[n1];
    // issue both scattered row loads before either write
    float4 v0, v1;
    if (r0 < KK) v0 = ((const float4*)(x + (size_t)n0 * DD))[lane];
    if (r1 < KK) v1 = ((const float4*)(x + (size_t)n1 * DD))[lane];
    if (r0 < KK) ((float4*)(out + (size_t)r0 * DD))[lane] = v0;
    if (r1 < KK) ((float4*)(out + (size_t)r1 * DD))[lane] = v1;
    if (lane == 0) {
        const int OFF_PERM  = KK * DD + 2 * NKEEP;
        const int OFF_BATCH = OFF_PERM + KK;
        const int OFF_W     = OFF_BATCH + KK;
        #pragma unroll
        for (int q = 0; q < 2; q++) {
            int node = n0 + q;
            int r = (q == 0) ? r0 : r1;
            if (r < KK) {
                long long bv;
                if (g_is64) bv = ((const long long*)batch)[node];
                else        bv = (long long)((const int*)batch)[node];
                out[OFF_PERM + r]  = (float)node;
                out[OFF_BATCH + r] = (float)bv;
                out[OFF_W + r]     = g_wf[node];
            }
        }
    }

    // ---- emit: blocks 0..31 ----
    if (blockIdx.x < 32) {
        __shared__ u32 words[256];
        __shared__ int wpref[256];
        __shared__ int warpsum[8];

        #pragma unroll
        for (int q = 0; q < 32; q++) {
            int n2 = q * 256 + tid;
            int uns = (g_rank[n2] >= KK) ? 1 : 0;
            u32 w = __ballot_sync(0xffffffffu, uns);
            if (lane == 0) words[q * 8 + wid] = w;
        }
        __syncthreads();

        int c = __popc(words[tid]);
        int v = c;
        #pragma unroll
        for (int o = 1; o < 32; o <<= 1) {
            int t = __shfl_up_sync(0xffffffffu, v, o);
            if (lane >= o) v += t;
        }
        if (lane == 31) warpsum[wid] = v;
        __syncthreads();
        if (wid == 0) {
            int s = (lane < 8) ? warpsum[lane] : 0;
            #pragma unroll
            for (int o = 1; o < 8; o <<= 1) {
                int t = __shfl_up_sync(0xffffffffu, s, o);
                if (lane >= o) s += t;
            }
            if (lane < 8) warpsum[lane] = s;
        }
        __syncthreads();
        wpref[tid] = v - c + ((wid > 0) ? warpsum[wid - 1] : 0);
        __syncthreads();

        int i = blockIdx.x * 256 + tid;
        if (g_rank[i] >= KK) {               // kept edge slot
            int word = i >> 5;
            u32 w = words[word];
            int pos = wpref[word] + __popc(w & ((1u << (i & 31)) - 1u));
            int a = g_ei[i], b = g_ej[i];
            int ra = g_rank[a], rb = g_rank[b];
            const int OFF_E = KK * DD;
            out[OFF_E + pos]         = (float)((ra < KK) ? ra : 0);
            out[OFF_E + NKEEP + pos] = (float)((rb < KK) ? rb : 0);
        }
    }

    // ---- restore zero-invariants: blocks 480..511 ----
    if (blockIdx.x >= 480) {
        int e = (blockIdx.x - 480) * 256 + tid;
        g_adj[g_ei[e] * WPR + (g_ej[e] >> 5)] = 0u;
        g_cnt[e] = 0;
    }
}

// ---------------- launch (PDL-chained) ----------------
static void launch_pdl(void* fn, dim3 grid, dim3 block, void** args) {
    cudaLaunchConfig_t cfg = {};
    cfg.gridDim = grid;
    cfg.blockDim = block;
    cudaLaunchAttribute attr[1];
    attr[0].id = cudaLaunchAttributeProgrammaticStreamSerialization;
    attr[0].val.programmaticStreamSerializationAllowed = 1;
    cfg.attrs = attr;
    cfg.numAttrs = 1;
    cudaLaunchKernelExC(&cfg, fn, args);
}

extern "C" void kernel_launch(void* const* d_in, const int* in_sizes, int n_in,
                              void* d_out, int out_size) {
    const float* x     = (const float*)d_in[0];
    const void*  edges = d_in[1];
    const void*  batch = d_in[2];
    float* out = (float*)d_out;

    k1_norms_pack<<<256, 256>>>(x, edges);

    {   // k3 (dependent on k1)
        void* args[] = { (void*)&x };
        launch_pdl((void*)k3_weights, dim3(1024), dim3(256), args);
    }
    {   // k4a (dependent on k3)
        void* args[] = {};
        launch_pdl((void*)k4a_rank, dim3(512), dim3(256), args);
    }
    {   // k45 (dependent on k4a)
        void* args[] = { (void*)&x, (void*)&batch, (void*)&out };
        launch_pdl((void*)k45_emit_gather, dim3(512), dim3(256), args);
    }
}